// round 2
// baseline (speedup 1.0000x reference)
#include <cuda_runtime.h>
#include <cstdint>

// ---------------- problem-size constants ----------------
#define NMAX 50048          // max nodes supported (problem uses 50000)
#define D_EDGE_K 268        // edge feature dim
#define D_OUT 128           // output dim
#define TE 64               // edges per tile
#define ETHREADS 128

// ---------------- scratch (device globals; no allocation allowed) ----------------
__device__ __align__(16) float g_Q[NMAX * 12];        // per-node frame, 3 x float4 rows (b1,n0,c per component)
__device__ __align__(16) float g_WTe[D_EDGE_K * 128]; // edge_W transposed  [k][j]
__device__ __align__(16) float g_WTn[96 * 128];       // node_W transposed  [k][j]

__constant__ int c_EPA[16] = {1,1,2,1,0,1,3,2,2,0,2,3,0,0,3,3};
__constant__ int c_EPB[16] = {1,2,1,0,1,3,1,2,0,2,3,2,0,3,0,3};
__constant__ int c_NPA[6]  = {1,1,1,0,0,3};
__constant__ int c_NPB[6]  = {0,2,3,2,3,2};
__constant__ int c_DSEL[4] = {1,0,2,3};

// ---------------- packed f32x2 helpers ----------------
__device__ __forceinline__ void fma2(unsigned long long& d, unsigned long long a, unsigned long long b) {
    asm("fma.rn.f32x2 %0, %1, %2, %0;" : "+l"(d) : "l"(a), "l"(b));
}
__device__ __forceinline__ unsigned long long dup2(float x) {
    unsigned long long d; unsigned int u = __float_as_uint(x);
    asm("mov.b64 %0, {%1, %1};" : "=l"(d) : "r"(u));
    return d;
}
__device__ __forceinline__ float2 unpk(unsigned long long v) {
    float2 r; asm("mov.b64 {%0, %1}, %2;" : "=f"(r.x), "=f"(r.y) : "l"(v));
    return r;
}

// ---------------- small math helpers ----------------
struct F3 { float x, y, z; };
__device__ __forceinline__ F3 f3sub(F3 a, F3 b) { return {a.x-b.x, a.y-b.y, a.z-b.z}; }
__device__ __forceinline__ F3 f3cross(F3 a, F3 b) {
    return {a.y*b.z - a.z*b.y, a.z*b.x - a.x*b.z, a.x*b.y - a.y*b.x};
}
__device__ __forceinline__ F3 f3nrm(F3 v) {
    float n = sqrtf(v.x*v.x + v.y*v.y + v.z*v.z);
    if (n == 0.0f) n = 1.0f;
    float i = 1.0f / n;
    return {v.x*i, v.y*i, v.z*i};
}

// ---------------- generic transpose: dst[c*R + r] = src[r*C + c] ----------------
__global__ void transpose_kernel(const float* __restrict__ src, float* __restrict__ dst, int R, int C) {
    int i = blockIdx.x * 256 + threadIdx.x;
    if (i < R * C) {
        int r = i / C, c = i - r * C;
        dst[c * R + r] = src[i];
    }
}

// ---------------- per-node orientation frame Q ----------------
__global__ void q_kernel(const float* __restrict__ X, int N) {
    int n = blockIdx.x * blockDim.x + threadIdx.x;
    if (n >= N) return;
    float4* Qo = ((float4*)g_Q) + (size_t)n * 3;
    if (n == N - 1) {
        float4 z = make_float4(0.f, 0.f, 0.f, 0.f);
        Qo[0] = z; Qo[1] = z; Qo[2] = z;
        return;
    }
    const float* x = X + (size_t)n * 12;
    F3 X0 = {x[0], x[1], x[2]};
    F3 X1 = {x[3], x[4], x[5]};
    F3 X2 = {x[6], x[7], x[8]};
    F3 u0 = f3nrm(f3sub(X1, X0));
    F3 u1 = f3nrm(f3sub(X2, X1));
    F3 n0 = f3nrm(f3cross(u0, u1));
    F3 b1 = f3nrm(f3sub(u0, u1));
    F3 cc = f3cross(b1, n0);
    // row i = component i of (b1, n0, c)
    Qo[0] = make_float4(b1.x, n0.x, cc.x, 0.f);
    Qo[1] = make_float4(b1.y, n0.y, cc.y, 0.f);
    Qo[2] = make_float4(b1.z, n0.z, cc.z, 0.f);
}

// ---------------- node path: one warp per node ----------------
__global__ __launch_bounds__(256) void node_kernel(
    const float* __restrict__ X,
    const float* __restrict__ nb,
    const float* __restrict__ gn,
    const float* __restrict__ bn,
    float* __restrict__ out, int N)
{
    __shared__ float sfeat[8][96];
    int w = threadIdx.x >> 5, lane = threadIdx.x & 31;
    int n = blockIdx.x * 8 + w;
    int nn = (n < N) ? n : 0;
    const float* x = X + (size_t)nn * 12;

    float Dv = 0.f;
    {
        int p = (lane < 6) ? lane : 0;
        int a = c_NPA[p], b = c_NPB[p];
        float dx = x[a*3+0] - x[b*3+0];
        float dy = x[a*3+1] - x[b*3+1];
        float dz = x[a*3+2] - x[b*3+2];
        Dv = sqrtf(dx*dx + dy*dy + dz*dz + 1e-6f);
    }
#pragma unroll
    for (int i = 0; i < 3; i++) {
        int idx = i * 32 + lane;
        int p = idx >> 4, k = idx & 15;
        float Dp = __shfl_sync(0xffffffffu, Dv, p);
        float u = (Dp - (float)k * (20.0f/15.0f)) * 0.8f;
        sfeat[w][idx] = __expf(-u * u);
    }
    __syncwarp();

    float a0 = 0.f, a1 = 0.f, a2 = 0.f, a3 = 0.f;
    const float4* Wp = (const float4*)g_WTn;
#pragma unroll 4
    for (int k = 0; k < 96; k++) {
        float f = sfeat[w][k];
        float4 wv = __ldg(&Wp[k * 32 + lane]);
        a0 += f * wv.x; a1 += f * wv.y; a2 += f * wv.z; a3 += f * wv.w;
    }
    int j0 = lane * 4;
    float4 nbv = *(const float4*)(nb + j0);
    a0 += nbv.x; a1 += nbv.y; a2 += nbv.z; a3 += nbv.w;

    float s1 = a0 + a1 + a2 + a3;
    float s2 = a0*a0 + a1*a1 + a2*a2 + a3*a3;
#pragma unroll
    for (int m = 16; m; m >>= 1) {
        s1 += __shfl_xor_sync(0xffffffffu, s1, m);
        s2 += __shfl_xor_sync(0xffffffffu, s2, m);
    }
    float mean = s1 * (1.f/128.f);
    float var  = (s2 - s1 * mean) * (1.f/127.f);
    float inv  = 1.f / (sqrtf(var + 1e-6f) + 1e-6f);
    float4 g = *(const float4*)(gn + j0);
    float4 b = *(const float4*)(bn + j0);
    if (n < N) {
        float4 o;
        o.x = g.x * (a0 - mean) * inv + b.x;
        o.y = g.y * (a1 - mean) * inv + b.y;
        o.z = g.z * (a2 - mean) * inv + b.z;
        o.w = g.w * (a3 - mean) * inv + b.w;
        *(float4*)(out + (size_t)n * 128 + j0) = o;
    }
}

// ---------------- edge path: persistent CTAs, W in SMEM, fused feature+GEMM+LN ----------------
// SMEM layout (floats): Wsh[268*128], feat[268*64], sXs[64*12], sXd[64*12], sQ[64*12], sD[16*64], then 128 ints
#define SMEM_FLOATS (34304 + 17152 + 768*3 + 1024)
#define SMEM_BYTES  (SMEM_FLOATS*4 + 128*4)

__global__ __launch_bounds__(ETHREADS, 1) void edge_kernel(
    const float* __restrict__ X,
    const int* __restrict__ src,
    const int* __restrict__ dst,
    const float* __restrict__ eb,
    const float* __restrict__ ge,
    const float* __restrict__ be,
    float* __restrict__ out,
    int ecount)
{
    extern __shared__ float sm[];
    float* Wsh  = sm;
    float* feat = Wsh + 34304;
    float* sXs  = feat + 17152;
    float* sXd  = sXs + 768;
    float* sQ   = sXd + 768;
    float* sD   = sQ + 768;
    int*   sIdx = (int*)(sD + 1024);

    int tid = threadIdx.x;

    // load transposed W once per CTA
    for (int i = tid; i < 268 * 32; i += ETHREADS)
        ((float4*)Wsh)[i] = ((const float4*)g_WTe)[i];

    int eg = tid >> 4;          // edge group (8 edges)
    int jg = tid & 15;          // output group (8 outputs)
    int j0 = jg << 3;
    float4 ebA = *(const float4*)(eb + j0), ebB = *(const float4*)(eb + j0 + 4);
    float4 gA  = *(const float4*)(ge + j0), gB  = *(const float4*)(ge + j0 + 4);
    float4 bA  = *(const float4*)(be + j0), bB  = *(const float4*)(be + j0 + 4);
    int ntiles = (ecount + TE - 1) / TE;
    __syncthreads();

    for (int tile = blockIdx.x; tile < ntiles; tile += gridDim.x) {
        int base = tile * TE;

        // --- stage edge indices ---
        {
            int e = base + (tid & 63);
            if (e >= ecount) e = ecount - 1;
            sIdx[tid] = (tid < TE) ? src[e] : dst[e];
        }
        __syncthreads();

        // --- gather X(src), X(dst), Q(src) ---
        for (int t = tid; t < 192; t += ETHREADS) {
            int e = t / 3, r = t - e * 3;
            ((float4*)sXs)[e*3 + r] = ((const float4*)X)[(size_t)sIdx[e] * 3 + r];
            ((float4*)sXd)[e*3 + r] = ((const float4*)X)[(size_t)sIdx[64 + e] * 3 + r];
            ((float4*)sQ )[e*3 + r] = ((const float4*)g_Q)[(size_t)sIdx[e] * 3 + r];
        }
        __syncthreads();

        // --- 16 pair distances per edge ---
        for (int t = tid; t < 1024; t += ETHREADS) {
            int p = t >> 6, e = t & 63;
            int a = c_EPA[p], b = c_EPB[p];
            const float* xs = sXs + e*12 + a*3;
            const float* xd = sXd + e*12 + b*3;
            float dx = xs[0]-xd[0], dy = xs[1]-xd[1], dz = xs[2]-xd[2];
            sD[(p << 6) + e] = sqrtf(dx*dx + dy*dy + dz*dz + 1e-6f);
        }
        // --- 12 orientation features per edge (independent of sD) ---
        for (int t = tid; t < 256; t += ETHREADS) {
            int a = t >> 6, e = t & 63;
            const float* xs = sXs + e*12;
            const float* xd = sXd + e*12;
            const float* q  = sQ  + e*12;
            int da = c_DSEL[a];
            float v0 = xd[da*3+0] - xs[0];
            float v1 = xd[da*3+1] - xs[1];
            float v2 = xd[da*3+2] - xs[2];
            float d0 = q[0]*v0 + q[1]*v1 + q[2]*v2;
            float d1 = q[4]*v0 + q[5]*v1 + q[6]*v2;
            float d2 = q[8]*v0 + q[9]*v1 + q[10]*v2;
            float nn = sqrtf(d0*d0 + d1*d1 + d2*d2);
            if (nn == 0.0f) nn = 1.0f;
            float inv = 1.0f / nn;
            feat[(256 + a*3 + 0)*64 + e] = d0 * inv;
            feat[(256 + a*3 + 1)*64 + e] = d1 * inv;
            feat[(256 + a*3 + 2)*64 + e] = d2 * inv;
        }
        __syncthreads();

        // --- 256 RBF features per edge ---
        for (int t = tid; t < 16384; t += ETHREADS) {
            int kk = t >> 6, e = t & 63;
            float d = sD[((kk >> 4) << 6) + e];
            float u = (d - (float)(kk & 15) * (20.0f/15.0f)) * 0.8f;
            feat[(kk << 6) + e] = __expf(-u * u);
        }
        __syncthreads();

        // --- GEMM: 8 edges x 8 outputs per thread, packed f32x2 (edge pairs) ---
        unsigned long long acc[32];
#pragma unroll
        for (int i = 0; i < 32; i++) acc[i] = 0ull;
        const float* fb = feat + (eg << 3);
        const float4* wb = ((const float4*)Wsh) + (jg << 1);
#pragma unroll 2
        for (int k = 0; k < 268; k++) {
            ulonglong2 fA = *(const ulonglong2*)(fb + (k << 6));
            ulonglong2 fB = *(const ulonglong2*)(fb + (k << 6) + 4);
            float4 w0 = wb[(k << 5)];
            float4 w1 = wb[(k << 5) + 1];
            unsigned long long f[4] = {fA.x, fA.y, fB.x, fB.y};
            unsigned long long wd[8];
            wd[0] = dup2(w0.x); wd[1] = dup2(w0.y); wd[2] = dup2(w0.z); wd[3] = dup2(w0.w);
            wd[4] = dup2(w1.x); wd[5] = dup2(w1.y); wd[6] = dup2(w1.z); wd[7] = dup2(w1.w);
#pragma unroll
            for (int ep = 0; ep < 4; ep++)
#pragma unroll
                for (int jj = 0; jj < 8; jj++)
                    fma2(acc[ep*8 + jj], f[ep], wd[jj]);
        }

        // --- epilogue: bias + LayerNorm (reduce across the 16 jg lanes) + store ---
        float xv[8][8];
#pragma unroll
        for (int ep = 0; ep < 4; ep++)
#pragma unroll
            for (int jj = 0; jj < 8; jj++) {
                float2 v = unpk(acc[ep*8 + jj]);
                xv[ep*2 + 0][jj] = v.x;
                xv[ep*2 + 1][jj] = v.y;
            }
        float ebv[8] = {ebA.x, ebA.y, ebA.z, ebA.w, ebB.x, ebB.y, ebB.z, ebB.w};
        float gv [8] = {gA.x,  gA.y,  gA.z,  gA.w,  gB.x,  gB.y,  gB.z,  gB.w};
        float bv [8] = {bA.x,  bA.y,  bA.z,  bA.w,  bB.x,  bB.y,  bB.z,  bB.w};
#pragma unroll
        for (int e = 0; e < 8; e++) {
            float s1 = 0.f, s2 = 0.f;
#pragma unroll
            for (int jj = 0; jj < 8; jj++) {
                float t = xv[e][jj] + ebv[jj];
                xv[e][jj] = t;
                s1 += t; s2 += t * t;
            }
#pragma unroll
            for (int m = 8; m; m >>= 1) {
                s1 += __shfl_xor_sync(0xffffffffu, s1, m);
                s2 += __shfl_xor_sync(0xffffffffu, s2, m);
            }
            float mean = s1 * (1.f/128.f);
            float var  = (s2 - s1 * mean) * (1.f/127.f);
            float inv  = 1.f / (sqrtf(var + 1e-6f) + 1e-6f);
            int eidx = base + (eg << 3) + e;
            if (eidx < ecount) {
                float4 o0, o1;
                o0.x = gv[0]*(xv[e][0]-mean)*inv + bv[0];
                o0.y = gv[1]*(xv[e][1]-mean)*inv + bv[1];
                o0.z = gv[2]*(xv[e][2]-mean)*inv + bv[2];
                o0.w = gv[3]*(xv[e][3]-mean)*inv + bv[3];
                o1.x = gv[4]*(xv[e][4]-mean)*inv + bv[4];
                o1.y = gv[5]*(xv[e][5]-mean)*inv + bv[5];
                o1.z = gv[6]*(xv[e][6]-mean)*inv + bv[6];
                o1.w = gv[7]*(xv[e][7]-mean)*inv + bv[7];
                float4* op = (float4*)(out + (size_t)eidx * 128 + j0);
                op[0] = o0;
                op[1] = o1;
            }
        }
        // no extra barrier needed: next tile's first __syncthreads orders feat reuse
    }
}

// ---------------- launch ----------------
extern "C" void kernel_launch(void* const* d_in, const int* in_sizes, int n_in,
                              void* d_out, int out_size)
{
    const float* X   = (const float*)d_in[0];
    const int*   Ein = (const int*)  d_in[1];
    const int*   Eex = (const int*)  d_in[2];
    const float* nW  = (const float*)d_in[3];
    const float* nb  = (const float*)d_in[4];
    const float* eW  = (const float*)d_in[5];
    const float* eb  = (const float*)d_in[6];
    const float* gn  = (const float*)d_in[7];
    const float* bn  = (const float*)d_in[8];
    const float* ge  = (const float*)d_in[9];
    const float* be  = (const float*)d_in[10];

    int N = in_sizes[0] / 12;
    int E = in_sizes[1] / 2;
    float* out = (float*)d_out;

    float* g_WTe_p = nullptr;
    float* g_WTn_p = nullptr;
    cudaGetSymbolAddress((void**)&g_WTe_p, g_WTe);
    cudaGetSymbolAddress((void**)&g_WTn_p, g_WTn);

    cudaFuncSetAttribute(edge_kernel, cudaFuncAttributeMaxDynamicSharedMemorySize, SMEM_BYTES);

    transpose_kernel<<<(128*268 + 255)/256, 256>>>(eW, g_WTe_p, 128, 268);
    transpose_kernel<<<(128*96  + 255)/256, 256>>>(nW, g_WTn_p, 128, 96);
    q_kernel<<<(N + 255)/256, 256>>>(X, N);

    node_kernel<<<(N + 7)/8, 256>>>(X, nb, gn, bn, out, N);

    float* outEin = out + (size_t)N * 128;
    float* outEex = outEin + (size_t)E * 128;
    edge_kernel<<<152, ETHREADS, SMEM_BYTES>>>(X, Ein, Ein + E, eb, ge, be, outEin, E);
    edge_kernel<<<152, ETHREADS, SMEM_BYTES>>>(X, Eex, Eex + E, eb, ge, be, outEex, E);
}

// round 7
// speedup vs baseline: 4.0913x; 4.0913x over previous
#include <cuda_runtime.h>
#include <cuda_fp16.h>
#include <cstdint>

// ---------------- constants ----------------
#define NMAX 50048
#define ETHREADS 256
#define EGRID 152
#define KS 280              // K stride in halves (560B: 8 ldmatrix rows conflict-free)

// ---------------- device scratch ----------------
__device__ __align__(16) float g_Q[NMAX * 12];
__device__ __align__(16) float g_WTn[96 * 128];
__device__ __align__(16) __half g_Whe[128 * KS];   // fp16 edge_W [j][k], k-padded

__constant__ int c_EPA[16] = {1,1,2,1,0,1,3,2,2,0,2,3,0,0,3,3};
__constant__ int c_EPB[16] = {1,2,1,0,1,3,1,2,0,2,3,2,0,3,0,3};
__constant__ int c_NPA[6]  = {1,1,1,0,0,3};
__constant__ int c_NPB[6]  = {0,2,3,2,3,2};
__constant__ int c_DSEL[4] = {1,0,2,3};

// ---------------- PTX helpers (baseline ISA only) ----------------
__device__ __forceinline__ uint32_t smem_u32(const void* p) {
    uint32_t a;
    asm("{ .reg .u64 t; cvta.to.shared.u64 t, %1; cvt.u32.u64 %0, t; }" : "=r"(a) : "l"(p));
    return a;
}
__device__ __forceinline__ void ldsm4(uint32_t& r0, uint32_t& r1, uint32_t& r2, uint32_t& r3, uint32_t a) {
    asm volatile("ldmatrix.sync.aligned.m8n8.x4.shared.b16 {%0,%1,%2,%3}, [%4];"
        : "=r"(r0), "=r"(r1), "=r"(r2), "=r"(r3) : "r"(a));
}
#define MMA16816(c, a0,a1,a2,a3, b0,b1) \
    asm volatile("mma.sync.aligned.m16n8k16.row.col.f32.f16.f16.f32 " \
        "{%0,%1,%2,%3}, {%4,%5,%6,%7}, {%8,%9}, {%0,%1,%2,%3};" \
        : "+f"((c)[0]), "+f"((c)[1]), "+f"((c)[2]), "+f"((c)[3]) \
        : "r"(a0), "r"(a1), "r"(a2), "r"(a3), "r"(b0), "r"(b1))

// ---------------- SMEM layout (bytes) ----------------
#define W_OFF   0
#define A_OFF   (128 * KS * 2)                 // 71680
#define XS_OFF  (A_OFF + 128 * KS * 2)         // 143360
#define XD_OFF  (XS_OFF + 6144)
#define Q_OFF   (XD_OFF + 6144)
#define SD_OFF  (Q_OFF + 6144)
#define IDX_OFF (SD_OFF + 8192)
#define EB_OFF  (IDX_OFF + 1024)
#define GE_OFF  (EB_OFF + 512)
#define BE_OFF  (GE_OFF + 512)
#define SMEM_E  (BE_OFF + 512)

// ---------------- small math ----------------
struct F3 { float x, y, z; };
__device__ __forceinline__ F3 f3sub(F3 a, F3 b) { return {a.x-b.x, a.y-b.y, a.z-b.z}; }
__device__ __forceinline__ F3 f3cross(F3 a, F3 b) {
    return {a.y*b.z - a.z*b.y, a.z*b.x - a.x*b.z, a.x*b.y - a.y*b.x};
}
__device__ __forceinline__ F3 f3nrm(F3 v) {
    float n = sqrtf(v.x*v.x + v.y*v.y + v.z*v.z);
    if (n == 0.0f) n = 1.0f;
    float i = 1.0f / n;
    return {v.x*i, v.y*i, v.z*i};
}

// ---------------- prep kernels ----------------
__global__ void transpose_kernel(const float* __restrict__ src, float* __restrict__ dst, int R, int C) {
    int i = blockIdx.x * 256 + threadIdx.x;
    if (i < R * C) { int r = i / C, c = i - r * C; dst[c * R + r] = src[i]; }
}

__global__ void wprep_kernel(const float* __restrict__ eW) {
    int idx = blockIdx.x * 256 + threadIdx.x;
    if (idx >= 128 * KS) return;
    int j = idx / KS, k = idx - j * KS;
    float v = (k < 268) ? eW[j * 268 + k] : 0.0f;
    g_Whe[j * KS + k] = __float2half_rn(v);
}

__global__ void q_kernel(const float* __restrict__ X, int N) {
    int n = blockIdx.x * blockDim.x + threadIdx.x;
    if (n >= N) return;
    float4* Qo = ((float4*)g_Q) + (size_t)n * 3;
    if (n == N - 1) {
        float4 z = make_float4(0.f, 0.f, 0.f, 0.f);
        Qo[0] = z; Qo[1] = z; Qo[2] = z;
        return;
    }
    const float* x = X + (size_t)n * 12;
    F3 X0 = {x[0], x[1], x[2]};
    F3 X1 = {x[3], x[4], x[5]};
    F3 X2 = {x[6], x[7], x[8]};
    F3 u0 = f3nrm(f3sub(X1, X0));
    F3 u1 = f3nrm(f3sub(X2, X1));
    F3 n0 = f3nrm(f3cross(u0, u1));
    F3 b1 = f3nrm(f3sub(u0, u1));
    F3 cc = f3cross(b1, n0);
    Qo[0] = make_float4(b1.x, n0.x, cc.x, 0.f);
    Qo[1] = make_float4(b1.y, n0.y, cc.y, 0.f);
    Qo[2] = make_float4(b1.z, n0.z, cc.z, 0.f);
}

// ---------------- node path (proven R1 version) ----------------
__global__ __launch_bounds__(256) void node_kernel(
    const float* __restrict__ X,
    const float* __restrict__ nb,
    const float* __restrict__ gn,
    const float* __restrict__ bn,
    float* __restrict__ out, int N)
{
    __shared__ float sfeat[8][96];
    int w = threadIdx.x >> 5, lane = threadIdx.x & 31;
    int n = blockIdx.x * 8 + w;
    int nn = (n < N) ? n : 0;
    const float* x = X + (size_t)nn * 12;

    float Dv = 0.f;
    {
        int p = (lane < 6) ? lane : 0;
        int a = c_NPA[p], b = c_NPB[p];
        float dx = x[a*3+0] - x[b*3+0];
        float dy = x[a*3+1] - x[b*3+1];
        float dz = x[a*3+2] - x[b*3+2];
        Dv = sqrtf(dx*dx + dy*dy + dz*dz + 1e-6f);
    }
#pragma unroll
    for (int i = 0; i < 3; i++) {
        int idx = i * 32 + lane;
        int p = idx >> 4, k = idx & 15;
        float Dp = __shfl_sync(0xffffffffu, Dv, p);
        float u = (Dp - (float)k * (20.0f/15.0f)) * 0.8f;
        sfeat[w][idx] = __expf(-u * u);
    }
    __syncwarp();

    float a0 = 0.f, a1 = 0.f, a2 = 0.f, a3 = 0.f;
    const float4* Wp = (const float4*)g_WTn;
#pragma unroll 4
    for (int k = 0; k < 96; k++) {
        float f = sfeat[w][k];
        float4 wv = __ldg(&Wp[k * 32 + lane]);
        a0 += f * wv.x; a1 += f * wv.y; a2 += f * wv.z; a3 += f * wv.w;
    }
    int j0 = lane * 4;
    float4 nbv = *(const float4*)(nb + j0);
    a0 += nbv.x; a1 += nbv.y; a2 += nbv.z; a3 += nbv.w;

    float s1 = a0 + a1 + a2 + a3;
    float s2 = a0*a0 + a1*a1 + a2*a2 + a3*a3;
#pragma unroll
    for (int m = 16; m; m >>= 1) {
        s1 += __shfl_xor_sync(0xffffffffu, s1, m);
        s2 += __shfl_xor_sync(0xffffffffu, s2, m);
    }
    float mean = s1 * (1.f/128.f);
    float var  = (s2 - s1 * mean) * (1.f/127.f);
    float inv  = 1.f / (sqrtf(var + 1e-6f) + 1e-6f);
    float4 g = *(const float4*)(gn + j0);
    float4 b = *(const float4*)(bn + j0);
    if (n < N) {
        float4 o;
        o.x = g.x * (a0 - mean) * inv + b.x;
        o.y = g.y * (a1 - mean) * inv + b.y;
        o.z = g.z * (a2 - mean) * inv + b.z;
        o.w = g.w * (a3 - mean) * inv + b.w;
        *(float4*)(out + (size_t)n * 128 + j0) = o;
    }
}

// ---------------- edge path: mma.sync (HMMA) 128x128 tiles ----------------
__global__ __launch_bounds__(ETHREADS, 1) void edge_kernel(
    const float* __restrict__ X,
    const int* __restrict__ src,
    const int* __restrict__ dst,
    const float* __restrict__ eb,
    const float* __restrict__ ge,
    const float* __restrict__ be,
    float* __restrict__ out,
    int E)
{
    extern __shared__ char sm[];
    uint32_t smb = smem_u32(sm);
    int tid = threadIdx.x;
    int w = tid >> 5, lane = tid & 31;

    __half* Ah = (__half*)(sm + A_OFF);

    // one-time setup
    if (tid < 128) {
        ((float*)(sm + EB_OFF))[tid] = eb[tid];
        ((float*)(sm + GE_OFF))[tid] = ge[tid];
        ((float*)(sm + BE_OFF))[tid] = be[tid];
        *(unsigned long long*)(Ah + tid * KS + 268) = 0ull;   // zero-pad k=268..271
    }
    for (int i = tid; i < 128 * KS / 8; i += ETHREADS)
        ((uint4*)(sm + W_OFF))[i] = ((const uint4*)g_Whe)[i];
    __syncthreads();

    float* sXs = (float*)(sm + XS_OFF);
    float* sXd = (float*)(sm + XD_OFF);
    float* sQ  = (float*)(sm + Q_OFF);
    float* sD  = (float*)(sm + SD_OFF);
    int*   sIdx = (int*)(sm + IDX_OFF);

    // ldmatrix lane address components
    int lm = lane >> 3, lr = lane & 7;
    // A: rows w*16 + (lm&1)*8 + lr, col offset (lm>>1)*8
    uint32_t aBase = smb + A_OFF + (uint32_t)(((w << 4) + ((lm & 1) << 3) + lr) * KS + ((lm >> 1) << 3)) * 2u;
    // B: rows (lm&1)*8 + lr (+ j0), col offset (lm>>1)*8
    uint32_t bBase = smb + W_OFF + (uint32_t)((((lm & 1) << 3) + lr) * KS + ((lm >> 1) << 3)) * 2u;

    int ntiles = (E + 127) >> 7;

    for (int tile = blockIdx.x; tile < ntiles; tile += gridDim.x) {
        int base = tile << 7;

        // stage indices
        {
            int e = base + (tid & 127);
            if (e >= E) e = E - 1;
            sIdx[tid] = (tid < 128) ? src[e] : dst[e];
        }
        __syncthreads();

        // gather X(src), X(dst), Q(src)
        {
            const float4* X4 = (const float4*)X;
            const float4* Q4 = (const float4*)g_Q;
            for (int t = tid; t < 384; t += ETHREADS) {
                int e = t / 3, r = t - e * 3;
                ((float4*)sXs)[t] = X4[(size_t)sIdx[e] * 3 + r];
                ((float4*)sXd)[t] = X4[(size_t)sIdx[128 + e] * 3 + r];
                ((float4*)sQ )[t] = Q4[(size_t)sIdx[e] * 3 + r];
            }
        }
        __syncthreads();

        // distances: 16 pairs x 128 edges
        for (int t = tid; t < 2048; t += ETHREADS) {
            int p = t >> 7, e = t & 127;
            int a = c_EPA[p], b = c_EPB[p];
            const float* xs = sXs + e*12 + a*3;
            const float* xd = sXd + e*12 + b*3;
            float dx = xs[0]-xd[0], dy = xs[1]-xd[1], dz = xs[2]-xd[2];
            sD[(p << 7) + e] = sqrtf(dx*dx + dy*dy + dz*dz + 1e-6f);
        }
        // direct features: k = 256..267
        {
            int e = tid & 127, hf = tid >> 7;
            const float* xs = sXs + e*12;
            const float* xd = sXd + e*12;
            const float* q  = sQ  + e*12;
#pragma unroll
            for (int ii = 0; ii < 2; ii++) {
                int a = hf * 2 + ii;
                int da = c_DSEL[a];
                float v0 = xd[da*3+0] - xs[0];
                float v1 = xd[da*3+1] - xs[1];
                float v2 = xd[da*3+2] - xs[2];
                float d0 = q[0]*v0 + q[1]*v1 + q[2]*v2;
                float d1 = q[4]*v0 + q[5]*v1 + q[6]*v2;
                float d2 = q[8]*v0 + q[9]*v1 + q[10]*v2;
                float nn = sqrtf(d0*d0 + d1*d1 + d2*d2);
                if (nn == 0.0f) nn = 1.0f;
                float inv = 1.0f / nn;
                int k = 256 + a * 3;
                Ah[e * KS + k]     = __float2half_rn(d0 * inv);
                Ah[e * KS + k + 1] = __float2half_rn(d1 * inv);
                Ah[e * KS + k + 2] = __float2half_rn(d2 * inv);
            }
        }
        __syncthreads();

        // RBF: 256 features per edge; thread (e, hf) does 8 mus for all 16 pairs
        {
            int e = tid & 127, hf = tid >> 7;
            int r0 = hf * 8;
#pragma unroll 1
            for (int p = 0; p < 16; p++) {
                float d = sD[(p << 7) + e];
                uint32_t pk[4];
#pragma unroll
                for (int j2 = 0; j2 < 4; j2++) {
                    float u0 = (d - (float)(r0 + 2*j2)     * (20.0f/15.0f)) * 0.8f;
                    float u1 = (d - (float)(r0 + 2*j2 + 1) * (20.0f/15.0f)) * 0.8f;
                    __half2 h = __floats2half2_rn(__expf(-u0*u0), __expf(-u1*u1));
                    pk[j2] = *(uint32_t*)&h;
                }
                *(uint4*)(Ah + e * KS + p * 16 + r0) = make_uint4(pk[0], pk[1], pk[2], pk[3]);
            }
        }
        __syncthreads();

        // MMA: warp w computes edges w*16..+15 x all 128 outputs, K=272
        float acc[64];
#pragma unroll
        for (int i = 0; i < 64; i++) acc[i] = 0.f;

#pragma unroll 1
        for (int s = 0; s < 17; s++) {
            uint32_t koff = (uint32_t)(s * 16 * 2);
            uint32_t a0, a1, a2, a3;
            ldsm4(a0, a1, a2, a3, aBase + koff);
#pragma unroll
            for (int np = 0; np < 8; np++) {
                uint32_t b0, b1, b2, b3;
                ldsm4(b0, b1, b2, b3, bBase + koff + (uint32_t)(np * 16 * KS * 2));
                MMA16816(&acc[(np*2    ) * 4], a0, a1, a2, a3, b0, b2);
                MMA16816(&acc[(np*2 + 1) * 4], a0, a1, a2, a3, b1, b3);
            }
        }

        // epilogue: bias + in-quad LayerNorm + store
        {
            const float* sEB = (const float*)(sm + EB_OFF);
            const float* sGE = (const float*)(sm + GE_OFF);
            const float* sBE = (const float*)(sm + BE_OFF);
            int rlo = lane >> 2, q = lane & 3;
#pragma unroll
            for (int h = 0; h < 2; h++) {
                float s1 = 0.f, s2 = 0.f;
#pragma unroll
                for (int nt = 0; nt < 16; nt++) {
                    int j = nt * 8 + q * 2;
                    float v0 = acc[nt*4 + h*2]     + sEB[j];
                    float v1 = acc[nt*4 + h*2 + 1] + sEB[j + 1];
                    acc[nt*4 + h*2]     = v0;
                    acc[nt*4 + h*2 + 1] = v1;
                    s1 += v0 + v1;
                    s2 += v0*v0 + v1*v1;
                }
                s1 += __shfl_xor_sync(0xffffffffu, s1, 1);
                s2 += __shfl_xor_sync(0xffffffffu, s2, 1);
                s1 += __shfl_xor_sync(0xffffffffu, s1, 2);
                s2 += __shfl_xor_sync(0xffffffffu, s2, 2);
                float mean = s1 * (1.f/128.f);
                float var  = (s2 - s1 * mean) * (1.f/127.f);
                float inv  = 1.f / (sqrtf(var + 1e-6f) + 1e-6f);
                int eidx = base + (w << 4) + rlo + h * 8;
                if (eidx < E) {
                    float* op = out + (size_t)eidx * 128;
#pragma unroll
                    for (int nt = 0; nt < 16; nt++) {
                        int j = nt * 8 + q * 2;
                        float2 ov;
                        ov.x = sGE[j]     * (acc[nt*4 + h*2]     - mean) * inv + sBE[j];
                        ov.y = sGE[j + 1] * (acc[nt*4 + h*2 + 1] - mean) * inv + sBE[j + 1];
                        *(float2*)(op + j) = ov;
                    }
                }
            }
        }
        // next tile's post-staging __syncthreads orders A reuse vs this tile's ldmatrix reads
    }
}

// ---------------- launch ----------------
extern "C" void kernel_launch(void* const* d_in, const int* in_sizes, int n_in,
                              void* d_out, int out_size)
{
    const float* X   = (const float*)d_in[0];
    const int*   Ein = (const int*)  d_in[1];
    const int*   Eex = (const int*)  d_in[2];
    const float* nW  = (const float*)d_in[3];
    const float* nb  = (const float*)d_in[4];
    const float* eW  = (const float*)d_in[5];
    const float* eb  = (const float*)d_in[6];
    const float* gn  = (const float*)d_in[7];
    const float* bn  = (const float*)d_in[8];
    const float* ge  = (const float*)d_in[9];
    const float* be  = (const float*)d_in[10];

    int N = in_sizes[0] / 12;
    int E = in_sizes[1] / 2;
    float* out = (float*)d_out;

    float* g_WTn_p = nullptr;
    cudaGetSymbolAddress((void**)&g_WTn_p, g_WTn);

    cudaFuncSetAttribute(edge_kernel, cudaFuncAttributeMaxDynamicSharedMemorySize, SMEM_E);

    transpose_kernel<<<(128*96 + 255)/256, 256>>>(nW, g_WTn_p, 128, 96);
    wprep_kernel<<<(128*KS + 255)/256, 256>>>(eW);
    q_kernel<<<(N + 255)/256, 256>>>(X, N);

    node_kernel<<<(N + 7)/8, 256>>>(X, nb, gn, bn, out, N);

    float* outEin = out + (size_t)N * 128;
    float* outEex = outEin + (size_t)E * 128;
    edge_kernel<<<EGRID, ETHREADS, SMEM_E>>>(X, Ein, Ein + E, eb, ge, be, outEin, E);
    edge_kernel<<<EGRID, ETHREADS, SMEM_E>>>(X, Eex, Eex + E, eb, ge, be, outEex, E);
}